// round 9
// baseline (speedup 1.0000x reference)
#include <cuda_runtime.h>
#include <cuda_fp16.h>
#include <cuda_bf16.h>
#include <cstdint>

#define B   32
#define N   2048
#define VD  256
#define LR  64
#define EMB 256
#define ROWS (B*N)
#define EPS_DIAG 1e-6f
#define EPS_BN   1e-5f

// Scratch (device globals)
__device__ float g_W[128 * 256];       // interleaved: row c even -> W1[c/2], odd -> W2[c/2]
__device__ float g_bias[128];
__device__ float g_s[B * LR];
__device__ float g_T[B * LR * VD];     // 2 MB: T[b][l][d]
__device__ float g_colsum[B * VD];
__device__ float g_vfinal[B * VD];

// dynamic smem layout for k_main (bytes)
#define SM_AS    0                      // V_hi fp16: u32[128][132]
#define SM_VLO   67584                  // V_lo fp16: u32[128][132]
#define SM_BS    135168                 // W fp16 2-stage: u32[2][128][36]
#define SM_RHI   172032                 // R_hi fp16[128][72]
#define SM_RLO   190464                 // R_lo fp16[128][72]
#define SM_D     208896                 // d_sh float[128]
#define SM_S     209408                 // s_sh float[64]
#define SM_BIAS  209664                 // bias float[128]
#define SMEM_MAIN 210176

__device__ __forceinline__ uint32_t pack_h2(float lo, float hi) {
    __half2 h = __floats2half2_rn(lo, hi);
    return *(uint32_t*)&h;
}

// hi = fp16(x,y); lo = fp16(residual)
__device__ __forceinline__ uint32_t pack_hi_lo(float x, float y, uint32_t& lo_bits) {
    __half2 h = __floats2half2_rn(x, y);
    float2 hf = __half22float2(h);
    __half2 l = __floats2half2_rn(x - hf.x, y - hf.y);
    lo_bits = *(uint32_t*)&l;
    return *(uint32_t*)&h;
}

__device__ __forceinline__ void mma_f16(float c[4], const uint32_t a[4], const uint32_t b[2]) {
    asm volatile(
        "mma.sync.aligned.m16n8k16.row.col.f32.f16.f16.f32 "
        "{%0,%1,%2,%3}, {%4,%5,%6,%7}, {%8,%9}, {%0,%1,%2,%3};"
        : "+f"(c[0]), "+f"(c[1]), "+f"(c[2]), "+f"(c[3])
        : "r"(a[0]), "r"(a[1]), "r"(a[2]), "r"(a[3]), "r"(b[0]), "r"(b[1]));
}

__device__ __forceinline__ void ldsm_x4(uint32_t r[4], uint32_t addr) {
    asm volatile("ldmatrix.sync.aligned.m8n8.x4.shared.b16 {%0,%1,%2,%3}, [%4];"
        : "=r"(r[0]), "=r"(r[1]), "=r"(r[2]), "=r"(r[3]) : "r"(addr));
}

__device__ __forceinline__ void ldsm_x4_t(uint32_t r[4], uint32_t addr) {
    asm volatile("ldmatrix.sync.aligned.m8n8.x4.trans.shared.b16 {%0,%1,%2,%3}, [%4];"
        : "=r"(r[0]), "=r"(r[1]), "=r"(r[2]), "=r"(r[3]) : "r"(addr));
}

// ---------------------------------------------------------------------------
// Kernel A: weight norm + zero accumulators.  grid 128, block 256
__global__ void k_weightnorm(const float* __restrict__ U1_v, const float* __restrict__ U1_g,
                             const float* __restrict__ U1_b, const float* __restrict__ U2_v,
                             const float* __restrict__ U2_g, const float* __restrict__ U2_b)
{
    int row = blockIdx.x;
    int l = row >> 1;
    bool odd = row & 1;
    const float* v = (odd ? U2_v : U1_v) + l * VD;
    const float* g = odd ? U2_g : U1_g;
    const float* bb = odd ? U2_b : U1_b;
    int tid = threadIdx.x;

    float x = v[tid];
    float ss = x * x;
    #pragma unroll
    for (int off = 16; off >= 1; off >>= 1) ss += __shfl_xor_sync(0xffffffff, ss, off);
    __shared__ float warp_ss[8];
    __shared__ float scale_sh;
    if ((tid & 31) == 0) warp_ss[tid >> 5] = ss;
    __syncthreads();
    if (tid == 0) {
        float tot = 0.f;
        #pragma unroll
        for (int w = 0; w < 8; w++) tot += warp_ss[w];
        scale_sh = g[l] * rsqrtf(tot);
    }
    __syncthreads();
    g_W[row * 256 + tid] = x * scale_sh;
    if (tid == 0) g_bias[row] = bb[l];

    int idx = blockIdx.x * 256 + tid;             // 0..32767
    for (int z = idx; z < B * LR * VD; z += 32768) g_T[z] = 0.f;
    if (idx < B * VD) g_colsum[idx] = 0.f;
    if (idx < B * LR) g_s[idx] = 0.f;
}

// ---------------------------------------------------------------------------
// Kernel C: fused double-GEMM per 128-row tile, with split-fp16 GEMM2.
//   V resident in smem as V_hi + V_lo.
//   GEMM1: acc = V_hi @ W^T (W 2-stage chunked)
//   epilogue: relu, d, dr, R_hi/R_lo = split(dr*right), s
//   GEMM2: T += R_hi^T V_hi + R_hi^T V_lo + R_lo^T V_hi   (fp32-accurate)
//   colsum: exact per-column sum of (hi+lo) from smem.
// grid 512, block 256 (8 warps), occ 1.
__global__ void __launch_bounds__(256, 1) k_main(const float* __restrict__ Vmat)
{
    extern __shared__ char smem[];
    uint32_t* As_u  = (uint32_t*)(smem + SM_AS);
    uint32_t* Vlo_u = (uint32_t*)(smem + SM_VLO);
    uint32_t* Bs_u  = (uint32_t*)(smem + SM_BS);
    __half*   Rhi   = (__half*)(smem + SM_RHI);
    __half*   Rlo   = (__half*)(smem + SM_RLO);
    float*    d_sh  = (float*)(smem + SM_D);
    float*    s_sh  = (float*)(smem + SM_S);
    float*    bias_sh = (float*)(smem + SM_BIAS);

    int tid = threadIdx.x;
    int lane = tid & 31, wid = tid >> 5;
    int warp_m = wid & 3, warp_n = wid >> 2;      // GEMM1: 32m x 64n per warp
    int qr = lane >> 2, qk = lane & 3;
    int l8 = lane & 7, lm = lane >> 3;
    int tileRow0 = blockIdx.x * 128;
    int batch = blockIdx.x >> 4;
    int lrow = tid >> 3;       // 0..31
    int lkq  = tid & 7;        // float4 slot low

    if (tid < 128) { d_sh[tid] = 0.f; bias_sh[tid] = g_bias[tid]; }
    if (tid < 64) s_sh[tid] = 0.f;

    uint32_t sAS  = (uint32_t)__cvta_generic_to_shared(smem + SM_AS);
    uint32_t sVLO = (uint32_t)__cvta_generic_to_shared(smem + SM_VLO);
    uint32_t sBS  = (uint32_t)__cvta_generic_to_shared(smem + SM_BS);
    uint32_t sRHI = (uint32_t)__cvta_generic_to_shared(smem + SM_RHI);
    uint32_t sRLO = (uint32_t)__cvta_generic_to_shared(smem + SM_RLO);

    // ---- load V tile, split into hi/lo fp16 ----
    const float* Vbase = Vmat + (size_t)tileRow0 * VD;
    #pragma unroll
    for (int i = 0; i < 4; i++) {
        int r = i * 32 + lrow;
        float4 v[8];
        #pragma unroll
        for (int p = 0; p < 8; p++) {
            int slot = lkq + 8 * p;
            v[p] = *(const float4*)(Vbase + (size_t)r * VD + slot * 4);
        }
        #pragma unroll
        for (int p = 0; p < 8; p++) {
            int kp = (lkq + 8 * p) * 2;
            uint32_t lo0, lo1;
            uint32_t hi0 = pack_hi_lo(v[p].x, v[p].y, lo0);
            uint32_t hi1 = pack_hi_lo(v[p].z, v[p].w, lo1);
            As_u[r * 132 + kp]      = hi0;
            As_u[r * 132 + kp + 1]  = hi1;
            Vlo_u[r * 132 + kp]     = lo0;
            Vlo_u[r * 132 + kp + 1] = lo1;
        }
    }
    __syncthreads();

    // prefetch W chunk 0
    float4 rb[4];
    #pragma unroll
    for (int i = 0; i < 4; i++)
        rb[i] = *(const float4*)(g_W + (i * 32 + lrow) * 256 + lkq * 4);

    // ---- exact colsum of this tile (hi+lo), overlapped with W prefetch ----
    {
        int d = tid;
        int u = d >> 1;
        float sum = 0.f;
        #pragma unroll 8
        for (int r = 0; r < 128; r++) {
            __half2 ah = *(__half2*)&As_u[r * 132 + u];
            __half2 bh = *(__half2*)&Vlo_u[r * 132 + u];
            float2 af = __half22float2(ah);
            float2 bf = __half22float2(bh);
            sum += (d & 1) ? (af.y + bf.y) : (af.x + bf.x);
        }
        atomicAdd(&g_colsum[batch * VD + d], sum);
    }

    // ---- GEMM1 ldsm bases ----
    uint32_t a1_base[2], b1_rel[4];
    #pragma unroll
    for (int mt = 0; mt < 2; mt++) {
        int r = warp_m * 32 + mt * 16 + (lm & 1) * 8 + l8;
        a1_base[mt] = sAS + (uint32_t)(r * 132 + (lm >> 1) * 4) * 4;
    }
    #pragma unroll
    for (int j = 0; j < 4; j++) {
        int c = warp_n * 64 + (2 * j + (lm >> 1)) * 8 + l8;
        b1_rel[j] = (uint32_t)(c * 36 + (lm & 1) * 4) * 4;
    }

    float acc[2][8][4];
    #pragma unroll
    for (int mt = 0; mt < 2; mt++)
        #pragma unroll
        for (int nt = 0; nt < 8; nt++)
            #pragma unroll
            for (int c = 0; c < 4; c++) acc[mt][nt][c] = 0.f;

    // ---- GEMM1: 8 chunks of k=32, W double-buffered ----
    for (int kc = 0; kc < 8; kc++) {
        int st = kc & 1;
        __syncthreads();
        #pragma unroll
        for (int i = 0; i < 4; i++) {
            int r = i * 32 + lrow;
            Bs_u[st * 4608 + r * 36 + lkq * 2]     = pack_h2(rb[i].x, rb[i].y);
            Bs_u[st * 4608 + r * 36 + lkq * 2 + 1] = pack_h2(rb[i].z, rb[i].w);
        }
        if (kc < 7) {
            int k0 = (kc + 1) * 32;
            #pragma unroll
            for (int i = 0; i < 4; i++)
                rb[i] = *(const float4*)(g_W + (i * 32 + lrow) * 256 + k0 + lkq * 4);
        }
        __syncthreads();
        #pragma unroll
        for (int ks = 0; ks < 2; ks++) {
            uint32_t a_koff = (uint32_t)(kc * 16 + ks * 8) * 4;
            uint32_t b_koff = (uint32_t)(st * 18432 + ks * 32);
            uint32_t af[2][4];
            ldsm_x4(af[0], a1_base[0] + a_koff);
            ldsm_x4(af[1], a1_base[1] + a_koff);
            uint32_t bf[8][2];
            #pragma unroll
            for (int j = 0; j < 4; j++) {
                uint32_t t[4];
                ldsm_x4(t, sBS + b_koff + b1_rel[j]);
                bf[2 * j][0] = t[0]; bf[2 * j][1] = t[1];
                bf[2 * j + 1][0] = t[2]; bf[2 * j + 1][1] = t[3];
            }
            #pragma unroll
            for (int mt = 0; mt < 2; mt++)
                #pragma unroll
                for (int nt = 0; nt < 8; nt++)
                    mma_f16(acc[mt][nt], af[mt], bf[nt]);
        }
    }

    // ---- epilogue: bias+relu, d, dr, split R, s ----
    float be[8], bo[8];
    #pragma unroll
    for (int nt = 0; nt < 8; nt++) {
        int c0 = warp_n * 64 + nt * 8 + qk * 2;
        be[nt] = bias_sh[c0];
        bo[nt] = bias_sh[c0 + 1];
    }

    #pragma unroll
    for (int mt = 0; mt < 2; mt++) {
        #pragma unroll
        for (int h = 0; h < 2; h++) {
            float dpart = 0.f;
            #pragma unroll
            for (int nt = 0; nt < 8; nt++) {
                float rv = fmaxf(acc[mt][nt][h * 2]     + be[nt], 0.f);
                float lv = fmaxf(acc[mt][nt][h * 2 + 1] + bo[nt], 0.f);
                acc[mt][nt][h * 2] = rv;
                acc[mt][nt][h * 2 + 1] = lv;
                dpart = fmaf(rv, lv, dpart);
            }
            dpart += __shfl_xor_sync(0xffffffff, dpart, 1);
            dpart += __shfl_xor_sync(0xffffffff, dpart, 2);
            if (qk == 0) {
                int rl = warp_m * 32 + mt * 16 + h * 8 + qr;
                atomicAdd(&d_sh[rl], dpart);
            }
        }
    }
    __syncthreads();

    float s_t[8];
    #pragma unroll
    for (int nt = 0; nt < 8; nt++) s_t[nt] = 0.f;

    #pragma unroll
    for (int mt = 0; mt < 2; mt++) {
        #pragma unroll
        for (int h = 0; h < 2; h++) {
            int rl = warp_m * 32 + mt * 16 + h * 8 + qr;
            float dr = rsqrtf(d_sh[rl] + EPS_DIAG);
            #pragma unroll
            for (int nt = 0; nt < 8; nt++) {
                int p = warp_n * 32 + nt * 4 + qk;      // LR index 0..63
                float r = dr * acc[mt][nt][h * 2];
                __half hh = __float2half(r);
                Rhi[rl * 72 + p] = hh;
                Rlo[rl * 72 + p] = __float2half(r - __half2float(hh));
                s_t[nt] = fmaf(dr, acc[mt][nt][h * 2 + 1], s_t[nt]);
            }
        }
    }
    #pragma unroll
    for (int off = 4; off <= 16; off <<= 1)
        #pragma unroll
        for (int nt = 0; nt < 8; nt++)
            s_t[nt] += __shfl_xor_sync(0xffffffff, s_t[nt], off);
    if (qr == 0) {
        #pragma unroll
        for (int nt = 0; nt < 8; nt++)
            atomicAdd(&s_sh[warp_n * 32 + nt * 4 + qk], s_t[nt]);
    }
    __syncthreads();
    if (tid < 64) atomicAdd(&g_s[batch * LR + tid], s_sh[tid]);

    // ---- GEMM2: T[64][256] += Rhi^T Vhi + Rhi^T Vlo + Rlo^T Vhi ----
    int warp2_m = wid & 1, warp2_n = wid >> 1;

    uint32_t a2_rel[2], b2_rel[4];
    #pragma unroll
    for (int mt2 = 0; mt2 < 2; mt2++) {
        int l0 = warp2_m * 32 + mt2 * 16 + (lm & 1) * 8;
        int rm = (lm >> 1) * 8 + l8;
        a2_rel[mt2] = (uint32_t)rm * 144 + (uint32_t)l0 * 2;
    }
    #pragma unroll
    for (int j = 0; j < 4; j++) {
        int d0 = warp2_n * 64 + j * 16 + (lm >> 1) * 8;
        int rm = (lm & 1) * 8 + l8;
        b2_rel[j] = (uint32_t)rm * 528 + (uint32_t)d0 * 2;
    }

    float acc2[2][8][4];
    #pragma unroll
    for (int mt2 = 0; mt2 < 2; mt2++)
        #pragma unroll
        for (int nt2 = 0; nt2 < 8; nt2++)
            #pragma unroll
            for (int c = 0; c < 4; c++) acc2[mt2][nt2][c] = 0.f;

    uint32_t apass[3] = {sRHI, sRHI, sRLO};
    uint32_t bpass[3] = {sAS, sVLO, sAS};

    #pragma unroll
    for (int pass = 0; pass < 3; pass++) {
        uint32_t ab = apass[pass], bb2 = bpass[pass];
        #pragma unroll
        for (int ks2 = 0; ks2 < 8; ks2++) {
            uint32_t af2[2][4];
            ldsm_x4_t(af2[0], ab + a2_rel[0] + ks2 * 2304);
            ldsm_x4_t(af2[1], ab + a2_rel[1] + ks2 * 2304);
            uint32_t bf2[8][2];
            #pragma unroll
            for (int j = 0; j < 4; j++) {
                uint32_t t[4];
                ldsm_x4_t(t, bb2 + b2_rel[j] + ks2 * 8448);
                bf2[2 * j][0] = t[0]; bf2[2 * j][1] = t[1];
                bf2[2 * j + 1][0] = t[2]; bf2[2 * j + 1][1] = t[3];
            }
            #pragma unroll
            for (int mt2 = 0; mt2 < 2; mt2++)
                #pragma unroll
                for (int nt2 = 0; nt2 < 8; nt2++)
                    mma_f16(acc2[mt2][nt2], af2[mt2], bf2[nt2]);
        }
    }

    float* Tb = g_T + (size_t)batch * LR * VD;
    #pragma unroll
    for (int mt2 = 0; mt2 < 2; mt2++) {
        #pragma unroll
        for (int nt2 = 0; nt2 < 8; nt2++) {
            int lr0 = warp2_m * 32 + mt2 * 16 + qr;
            int dc  = warp2_n * 64 + nt2 * 8 + qk * 2;
            atomicAdd(&Tb[lr0 * VD + dc],           acc2[mt2][nt2][0]);
            atomicAdd(&Tb[lr0 * VD + dc + 1],       acc2[mt2][nt2][1]);
            atomicAdd(&Tb[(lr0 + 8) * VD + dc],     acc2[mt2][nt2][2]);
            atomicAdd(&Tb[(lr0 + 8) * VD + dc + 1], acc2[mt2][nt2][3]);
        }
    }
}

// ---------------------------------------------------------------------------
// Kernel D: combine. v_final[b,d] = ((N+1)*colsum - sum_l s_l T[l,d]) / N
// grid 32, block 256
__global__ void __launch_bounds__(256) k_comb()
{
    __shared__ float s_sh[64];
    int b = blockIdx.x;
    int tid = threadIdx.x;
    if (tid < 64) s_sh[tid] = g_s[b * LR + tid];
    __syncthreads();

    const float* Tb = g_T + (size_t)b * LR * VD + tid;
    float dot = 0.f;
    #pragma unroll 8
    for (int l = 0; l < 64; l++) dot = fmaf(s_sh[l], Tb[l * VD], dot);
    float cs = g_colsum[b * VD + tid];
    g_vfinal[b * VD + tid] = ((float)(N + 1) * cs - dot) * (1.0f / (float)N);
}

// ---------------------------------------------------------------------------
// Kernel E: feat = v_final @ W_lin^T + b_lin; BatchNorm over B (biased var).
// grid 256, block 128.
__global__ void __launch_bounds__(128) k_bn(const float* __restrict__ W_lin,
                                            const float* __restrict__ b_lin,
                                            const float* __restrict__ gamma,
                                            const float* __restrict__ beta,
                                            float* __restrict__ out)
{
    int e = blockIdx.x;
    int tid = threadIdx.x;
    __shared__ float4 w_sh[64];
    __shared__ float feats[32];

    if (tid < 64) w_sh[tid] = ((const float4*)(W_lin + e * VD))[tid];
    __syncthreads();

    int bat = tid >> 2;
    int q0  = tid & 3;
    const float4* vr = (const float4*)(g_vfinal + bat * VD);
    float dot = 0.f;
    #pragma unroll
    for (int q = 0; q < 16; q++) {
        float4 v = vr[q * 4 + q0];
        float4 w = w_sh[q * 4 + q0];
        dot = fmaf(v.x, w.x, dot);
        dot = fmaf(v.y, w.y, dot);
        dot = fmaf(v.z, w.z, dot);
        dot = fmaf(v.w, w.w, dot);
    }
    dot += __shfl_xor_sync(0xffffffff, dot, 1);
    dot += __shfl_xor_sync(0xffffffff, dot, 2);
    if (q0 == 0) feats[bat] = dot + b_lin[e];
    __syncthreads();

    if (tid < 32) {
        float f = feats[tid];
        float mu = f;
        #pragma unroll
        for (int off = 16; off >= 1; off >>= 1) mu += __shfl_xor_sync(0xffffffff, mu, off);
        mu *= (1.0f / 32.0f);
        float df = f - mu;
        float vv = df * df;
        #pragma unroll
        for (int off = 16; off >= 1; off >>= 1) vv += __shfl_xor_sync(0xffffffff, vv, off);
        vv *= (1.0f / 32.0f);
        out[tid * EMB + e] = df * rsqrtf(vv + EPS_BN) * gamma[e] + beta[e];
    }
}

// ---------------------------------------------------------------------------
extern "C" void kernel_launch(void* const* d_in, const int* in_sizes, int n_in,
                              void* d_out, int out_size)
{
    const float* Vmat  = (const float*)d_in[0];
    const float* U1_v  = (const float*)d_in[1];
    const float* U1_g  = (const float*)d_in[2];
    const float* U1_b  = (const float*)d_in[3];
    const float* U2_v  = (const float*)d_in[4];
    const float* U2_g  = (const float*)d_in[5];
    const float* U2_b  = (const float*)d_in[6];
    const float* W_lin = (const float*)d_in[7];
    const float* b_lin = (const float*)d_in[8];
    const float* gamma = (const float*)d_in[9];
    const float* beta  = (const float*)d_in[10];
    float* out = (float*)d_out;

    cudaFuncSetAttribute(k_main, cudaFuncAttributeMaxDynamicSharedMemorySize, SMEM_MAIN);

    k_weightnorm<<<128, 256>>>(U1_v, U1_g, U1_b, U2_v, U2_g, U2_b);
    k_main<<<ROWS / 128, 256, SMEM_MAIN>>>(Vmat);
    k_comb<<<B, 256>>>();
    k_bn<<<EMB, 128>>>(W_lin, b_lin, gamma, beta, out);
}

// round 11
// speedup vs baseline: 1.3626x; 1.3626x over previous
#include <cuda_runtime.h>
#include <cuda_fp16.h>
#include <cuda_bf16.h>
#include <cstdint>

#define B   32
#define N   2048
#define VD  256
#define LR  64
#define EMB 256
#define ROWS (B*N)
#define EPS_DIAG 1e-6f
#define EPS_BN   1e-5f

// Scratch (device globals)
__device__ float g_W[128 * 256];      // interleaved: row c even -> W1[c/2], odd -> W2[c/2]
__device__ float g_bias[128];
__device__ __half g_P[(size_t)ROWS * LR];   // 8 MB: P[m][l] = dr_m * right[m][l]
__device__ float g_s[B * LR];
__device__ float g_vfinal[B * VD];

__device__ __forceinline__ uint32_t pack_h2(float lo, float hi) {
    __half2 h = __floats2half2_rn(lo, hi);
    return *(uint32_t*)&h;
}

__device__ __forceinline__ void mma_f16(float c[4], const uint32_t a[4], const uint32_t b[2]) {
    asm volatile(
        "mma.sync.aligned.m16n8k16.row.col.f32.f16.f16.f32 "
        "{%0,%1,%2,%3}, {%4,%5,%6,%7}, {%8,%9}, {%0,%1,%2,%3};"
        : "+f"(c[0]), "+f"(c[1]), "+f"(c[2]), "+f"(c[3])
        : "r"(a[0]), "r"(a[1]), "r"(a[2]), "r"(a[3]), "r"(b[0]), "r"(b[1]));
}

__device__ __forceinline__ void ldsm_x4(uint32_t r[4], uint32_t addr) {
    asm volatile("ldmatrix.sync.aligned.m8n8.x4.shared.b16 {%0,%1,%2,%3}, [%4];"
        : "=r"(r[0]), "=r"(r[1]), "=r"(r[2]), "=r"(r[3]) : "r"(addr));
}

// ---------------------------------------------------------------------------
// Kernel A: weight norm + zero accumulators.  grid 128, block 256
__global__ void k_weightnorm(const float* __restrict__ U1_v, const float* __restrict__ U1_g,
                             const float* __restrict__ U1_b, const float* __restrict__ U2_v,
                             const float* __restrict__ U2_g, const float* __restrict__ U2_b)
{
    int row = blockIdx.x;
    int l = row >> 1;
    bool odd = row & 1;
    const float* v = (odd ? U2_v : U1_v) + l * VD;
    const float* g = odd ? U2_g : U1_g;
    const float* bb = odd ? U2_b : U1_b;
    int tid = threadIdx.x;

    float x = v[tid];
    float ss = x * x;
    #pragma unroll
    for (int off = 16; off >= 1; off >>= 1) ss += __shfl_xor_sync(0xffffffff, ss, off);
    __shared__ float warp_ss[8];
    __shared__ float scale_sh;
    if ((tid & 31) == 0) warp_ss[tid >> 5] = ss;
    __syncthreads();
    if (tid == 0) {
        float tot = 0.f;
        #pragma unroll
        for (int w = 0; w < 8; w++) tot += warp_ss[w];
        scale_sh = g[l] * rsqrtf(tot);
    }
    __syncthreads();
    g_W[row * 256 + tid] = x * scale_sh;
    if (tid == 0) g_bias[row] = bb[l];

    int idx = blockIdx.x * 256 + tid;
    if (idx < B * LR) g_s[idx] = 0.f;
    if (idx < B * VD) g_vfinal[idx] = 0.f;
}

// ---------------------------------------------------------------------------
// Kernel C: fp16 tensor-core GEMM [65536x256] @ W^T[256x128] + fused epilogue.
// (R7-measured structure; only change: stores P = dr*right as fp16.)
// grid 512 (row tiles of 128), block 256 (8 warps: 4 m x 2 n).
__global__ void __launch_bounds__(256, 2) k_main(const float* __restrict__ Vmat)
{
    __shared__ uint32_t As[128][36];   // [row][kpair] half2 bits; 16 used, pad 36
    __shared__ uint32_t Bs[128][36];   // [col][kpair]
    __shared__ float d_sh[128];
    __shared__ float s_sh[64];
    __shared__ float bias_sh[128];

    int tid = threadIdx.x;
    int lane = tid & 31, wid = tid >> 5;
    int warp_m = wid & 3, warp_n = wid >> 2;     // warp tile: 32 rows x 64 cols
    int qr = lane >> 2, qk = lane & 3;
    int tileRow0 = blockIdx.x * 128;
    int batch = blockIdx.x >> 4;                 // 16 tiles per batch

    if (tid < 128) { d_sh[tid] = 0.f; bias_sh[tid] = g_bias[tid]; }
    if (tid < 64) s_sh[tid] = 0.f;

    float acc[2][8][4];
    #pragma unroll
    for (int mt = 0; mt < 2; mt++)
        #pragma unroll
        for (int nt = 0; nt < 8; nt++)
            #pragma unroll
            for (int c = 0; c < 4; c++) acc[mt][nt][c] = 0.f;

    const float* Vbase = Vmat + (size_t)tileRow0 * VD;
    int lrow = tid >> 3;      // base row within the 32-row load slab
    int lkq  = tid & 7;       // float4 index within 32-k chunk

    // Per-lane ldmatrix base addresses (ks=0); ks=1 adds 32 bytes (8 kpairs).
    uint32_t sA = (uint32_t)__cvta_generic_to_shared(&As[0][0]);
    uint32_t sB = (uint32_t)__cvta_generic_to_shared(&Bs[0][0]);
    int l8 = lane & 7, lm = lane >> 3;   // lm = matrix index 0..3
    uint32_t a_base[2], b_base[4];
    #pragma unroll
    for (int mt = 0; mt < 2; mt++) {
        int row = warp_m * 32 + mt * 16 + (lm & 1) * 8 + l8;
        int kp  = (lm >> 1) * 4;
        a_base[mt] = sA + (uint32_t)(row * 36 + kp) * 4;
    }
    #pragma unroll
    for (int j = 0; j < 4; j++) {
        int c  = warp_n * 64 + (2 * j + (lm >> 1)) * 8 + l8;
        int kp = (lm & 1) * 4;
        b_base[j] = sB + (uint32_t)(c * 36 + kp) * 4;
    }

    float4 ra[4], rb[4];
    // prefetch chunk 0
    #pragma unroll
    for (int i = 0; i < 4; i++) {
        int r = i * 32 + lrow;
        ra[i] = *(const float4*)(Vbase + (size_t)r * VD + lkq * 4);
        rb[i] = *(const float4*)(g_W + r * 256 + lkq * 4);
    }

    for (int kc = 0; kc < 8; kc++) {
        __syncthreads();
        #pragma unroll
        for (int i = 0; i < 4; i++) {
            int r = i * 32 + lrow;
            As[r][lkq * 2]     = pack_h2(ra[i].x, ra[i].y);
            As[r][lkq * 2 + 1] = pack_h2(ra[i].z, ra[i].w);
            Bs[r][lkq * 2]     = pack_h2(rb[i].x, rb[i].y);
            Bs[r][lkq * 2 + 1] = pack_h2(rb[i].z, rb[i].w);
        }
        __syncthreads();
        if (kc < 7) {
            int k0 = (kc + 1) * 32;
            #pragma unroll
            for (int i = 0; i < 4; i++) {
                int r = i * 32 + lrow;
                ra[i] = *(const float4*)(Vbase + (size_t)r * VD + k0 + lkq * 4);
                rb[i] = *(const float4*)(g_W + r * 256 + k0 + lkq * 4);
            }
        }
        // chunk = 32 k = 2 mma k16-steps
        #pragma unroll
        for (int ks = 0; ks < 2; ks++) {
            uint32_t koff = ks * 32;
            uint32_t af[2][4];
            ldsm_x4(af[0], a_base[0] + koff);
            ldsm_x4(af[1], a_base[1] + koff);
            uint32_t bf[8][2];
            #pragma unroll
            for (int j = 0; j < 4; j++) {
                uint32_t t[4];
                ldsm_x4(t, b_base[j] + koff);
                bf[2 * j][0]     = t[0];
                bf[2 * j][1]     = t[1];
                bf[2 * j + 1][0] = t[2];
                bf[2 * j + 1][1] = t[3];
            }
            #pragma unroll
            for (int mt = 0; mt < 2; mt++)
                #pragma unroll
                for (int nt = 0; nt < 8; nt++)
                    mma_f16(acc[mt][nt], af[mt], bf[nt]);
        }
    }

    // ---- epilogue: bias+relu, d per row, dr, store P=dr*right (fp16), s ----
    float be[8], bo[8];
    #pragma unroll
    for (int nt = 0; nt < 8; nt++) {
        int c0 = warp_n * 64 + nt * 8 + qk * 2;
        be[nt] = bias_sh[c0];
        bo[nt] = bias_sh[c0 + 1];
    }

    #pragma unroll
    for (int mt = 0; mt < 2; mt++) {
        #pragma unroll
        for (int h = 0; h < 2; h++) {
            float dpart = 0.f;
            #pragma unroll
            for (int nt = 0; nt < 8; nt++) {
                float rv = fmaxf(acc[mt][nt][h * 2]     + be[nt], 0.f);
                float lv = fmaxf(acc[mt][nt][h * 2 + 1] + bo[nt], 0.f);
                acc[mt][nt][h * 2] = rv;
                acc[mt][nt][h * 2 + 1] = lv;
                dpart = fmaf(rv, lv, dpart);
            }
            dpart += __shfl_xor_sync(0xffffffff, dpart, 1);
            dpart += __shfl_xor_sync(0xffffffff, dpart, 2);
            if (qk == 0) {
                int rl = warp_m * 32 + mt * 16 + h * 8 + qr;
                atomicAdd(&d_sh[rl], dpart);
            }
        }
    }
    __syncthreads();

    float s_t[8];
    #pragma unroll
    for (int nt = 0; nt < 8; nt++) s_t[nt] = 0.f;

    #pragma unroll
    for (int mt = 0; mt < 2; mt++) {
        #pragma unroll
        for (int h = 0; h < 2; h++) {
            int rl = warp_m * 32 + mt * 16 + h * 8 + qr;
            float dr = rsqrtf(d_sh[rl] + EPS_DIAG);
            int row = tileRow0 + rl;
            __half* pp = g_P + (size_t)row * LR + warp_n * 32;
            #pragma unroll
            for (int nt = 0; nt < 8; nt++) {
                pp[nt * 4 + qk] = __float2half(dr * acc[mt][nt][h * 2]);
                s_t[nt] = fmaf(dr, acc[mt][nt][h * 2 + 1], s_t[nt]);
            }
        }
    }
    #pragma unroll
    for (int off = 4; off <= 16; off <<= 1)
        #pragma unroll
        for (int nt = 0; nt < 8; nt++)
            s_t[nt] += __shfl_xor_sync(0xffffffff, s_t[nt], off);
    if (qr == 0) {
        #pragma unroll
        for (int nt = 0; nt < 8; nt++)
            atomicAdd(&s_sh[warp_n * 32 + nt * 4 + qk], s_t[nt]);
    }
    __syncthreads();
    if (tid < 64) atomicAdd(&g_s[batch * LR + tid], s_sh[tid]);
}

// ---------------------------------------------------------------------------
// Kernel D: c[m] = N+1 - s.P[m]; v_final += (1/N)*c[m]*Vmat[m,:]
// grid (4, 32), block 256. Block covers 512 rows of one batch.
// Phase 2: 4 m-groups x 64 threads x float4 columns -> 128B in flight/thread.
__global__ void __launch_bounds__(256) k_final(const float* __restrict__ Vmat)
{
    __shared__ float s_sh[64];
    __shared__ float c_sh[512];
    __shared__ float red[4][256];
    int tid = threadIdx.x;
    int b = blockIdx.y;
    int m0 = blockIdx.x * 512;

    if (tid < 64) s_sh[tid] = g_s[b * LR + tid];
    __syncthreads();

    #pragma unroll
    for (int i = 0; i < 2; i++) {
        int row = b * N + m0 + tid + i * 256;
        const uint4* pp = (const uint4*)(g_P + (size_t)row * LR);   // 8 x 8 halves
        float dot = 0.f;
        #pragma unroll
        for (int q = 0; q < 8; q++) {
            uint4 u = pp[q];
            float2 f0 = __half22float2(*(__half2*)&u.x);
            float2 f1 = __half22float2(*(__half2*)&u.y);
            float2 f2 = __half22float2(*(__half2*)&u.z);
            float2 f3 = __half22float2(*(__half2*)&u.w);
            const float* sv = &s_sh[q * 8];
            dot = fmaf(f0.x, sv[0], dot); dot = fmaf(f0.y, sv[1], dot);
            dot = fmaf(f1.x, sv[2], dot); dot = fmaf(f1.y, sv[3], dot);
            dot = fmaf(f2.x, sv[4], dot); dot = fmaf(f2.y, sv[5], dot);
            dot = fmaf(f3.x, sv[6], dot); dot = fmaf(f3.y, sv[7], dot);
        }
        c_sh[tid + i * 256] = (float)(N + 1) - dot;
    }
    __syncthreads();

    int g = tid >> 6;            // m-group 0..3 (128 rows each)
    int c4 = (tid & 63) * 4;     // column base
    const float* Vp = Vmat + ((size_t)(b * N + m0 + g * 128)) * VD + c4;
    const float* cp = &c_sh[g * 128];
    float4 vac = make_float4(0.f, 0.f, 0.f, 0.f);
    #pragma unroll 8
    for (int j = 0; j < 128; j++) {
        float4 v = *(const float4*)(Vp + (size_t)j * VD);
        float cc = cp[j];
        vac.x = fmaf(cc, v.x, vac.x);
        vac.y = fmaf(cc, v.y, vac.y);
        vac.z = fmaf(cc, v.z, vac.z);
        vac.w = fmaf(cc, v.w, vac.w);
    }
    *(float4*)&red[g][c4] = vac;
    __syncthreads();

    float sum = red[0][tid] + red[1][tid] + red[2][tid] + red[3][tid];
    atomicAdd(&g_vfinal[b * VD + tid], sum * (1.0f / (float)N));
}

// ---------------------------------------------------------------------------
// Kernel E: feat = v_final @ W_lin^T + b_lin; BatchNorm over B (biased var).
// grid 256, block 128. (63.5us-measured version)
__global__ void __launch_bounds__(128) k_bn(const float* __restrict__ W_lin,
                                            const float* __restrict__ b_lin,
                                            const float* __restrict__ gamma,
                                            const float* __restrict__ beta,
                                            float* __restrict__ out)
{
    int e = blockIdx.x;
    int tid = threadIdx.x;
    __shared__ float4 w_sh[64];
    __shared__ float feats[32];

    if (tid < 64) w_sh[tid] = ((const float4*)(W_lin + e * VD))[tid];
    __syncthreads();

    int bat = tid >> 2;
    int q0  = tid & 3;
    const float4* vr = (const float4*)(g_vfinal + bat * VD);
    float dot = 0.f;
    #pragma unroll
    for (int q = 0; q < 16; q++) {
        float4 v = vr[q * 4 + q0];
        float4 w = w_sh[q * 4 + q0];
        dot = fmaf(v.x, w.x, dot);
        dot = fmaf(v.y, w.y, dot);
        dot = fmaf(v.z, w.z, dot);
        dot = fmaf(v.w, w.w, dot);
    }
    dot += __shfl_xor_sync(0xffffffff, dot, 1);
    dot += __shfl_xor_sync(0xffffffff, dot, 2);
    if (q0 == 0) feats[bat] = dot + b_lin[e];
    __syncthreads();

    if (tid < 32) {
        float f = feats[tid];
        float mu = f;
        #pragma unroll
        for (int off = 16; off >= 1; off >>= 1) mu += __shfl_xor_sync(0xffffffff, mu, off);
        mu *= (1.0f / 32.0f);
        float df = f - mu;
        float vv = df * df;
        #pragma unroll
        for (int off = 16; off >= 1; off >>= 1) vv += __shfl_xor_sync(0xffffffff, vv, off);
        vv *= (1.0f / 32.0f);
        out[tid * EMB + e] = df * rsqrtf(vv + EPS_BN) * gamma[e] + beta[e];
    }
}

// ---------------------------------------------------------------------------
extern "C" void kernel_launch(void* const* d_in, const int* in_sizes, int n_in,
                              void* d_out, int out_size)
{
    const float* Vmat  = (const float*)d_in[0];
    const float* U1_v  = (const float*)d_in[1];
    const float* U1_g  = (const float*)d_in[2];
    const float* U1_b  = (const float*)d_in[3];
    const float* U2_v  = (const float*)d_in[4];
    const float* U2_g  = (const float*)d_in[5];
    const float* U2_b  = (const float*)d_in[6];
    const float* W_lin = (const float*)d_in[7];
    const float* b_lin = (const float*)d_in[8];
    const float* gamma = (const float*)d_in[9];
    const float* beta  = (const float*)d_in[10];
    float* out = (float*)d_out;

    k_weightnorm<<<128, 256>>>(U1_v, U1_g, U1_b, U2_v, U2_g, U2_b);
    k_main<<<ROWS / 128, 256>>>(Vmat);
    k_final<<<dim3(4, B), 256>>>(Vmat);
    k_bn<<<EMB, 128>>>(W_lin, b_lin, gamma, beta, out);
}

// round 13
// speedup vs baseline: 1.3682x; 1.0042x over previous
#include <cuda_runtime.h>
#include <cuda_fp16.h>
#include <cuda_bf16.h>
#include <cstdint>

#define B   32
#define N   2048
#define VD  256
#define LR  64
#define EMB 256
#define ROWS (B*N)
#define EPS_DIAG 1e-6f
#define EPS_BN   1e-5f

// Scratch (device globals)
__device__ float g_W[128 * 256];      // interleaved: row c even -> W1[c/2], odd -> W2[c/2]
__device__ float g_bias[128];
__device__ __half g_P[(size_t)ROWS * LR];   // 8 MB: P[m][l] = dr_m * right[m][l]
__device__ float g_s[B * LR];
__device__ float g_vfinal[B * VD];

// k_main dynamic smem layout (bytes):
//   As: u32[2][128][36] @ 0        (36864)
//   Bs: u32[2][128][36] @ 36864    (36864)
//   d_sh: float[128]    @ 73728
//   s_sh: float[64]     @ 74240
//   bias: float[128]    @ 74496
#define SM_AS   0
#define SM_BS   36864
#define SM_D    73728
#define SM_S    74240
#define SM_BIAS 74496
#define SMEM_MAIN 75008

__device__ __forceinline__ uint32_t pack_h2(float lo, float hi) {
    __half2 h = __floats2half2_rn(lo, hi);
    return *(uint32_t*)&h;
}

__device__ __forceinline__ void mma_f16(float c[4], const uint32_t a[4], const uint32_t b[2]) {
    asm volatile(
        "mma.sync.aligned.m16n8k16.row.col.f32.f16.f16.f32 "
        "{%0,%1,%2,%3}, {%4,%5,%6,%7}, {%8,%9}, {%0,%1,%2,%3};"
        : "+f"(c[0]), "+f"(c[1]), "+f"(c[2]), "+f"(c[3])
        : "r"(a[0]), "r"(a[1]), "r"(a[2]), "r"(a[3]), "r"(b[0]), "r"(b[1]));
}

__device__ __forceinline__ void ldsm_x4(uint32_t r[4], uint32_t addr) {
    asm volatile("ldmatrix.sync.aligned.m8n8.x4.shared.b16 {%0,%1,%2,%3}, [%4];"
        : "=r"(r[0]), "=r"(r[1]), "=r"(r[2]), "=r"(r[3]) : "r"(addr));
}

// ---------------------------------------------------------------------------
// Kernel A: weight norm + zero accumulators.  grid 128, block 256
__global__ void k_weightnorm(const float* __restrict__ U1_v, const float* __restrict__ U1_g,
                             const float* __restrict__ U1_b, const float* __restrict__ U2_v,
                             const float* __restrict__ U2_g, const float* __restrict__ U2_b)
{
    int row = blockIdx.x;
    int l = row >> 1;
    bool odd = row & 1;
    const float* v = (odd ? U2_v : U1_v) + l * VD;
    const float* g = odd ? U2_g : U1_g;
    const float* bb = odd ? U2_b : U1_b;
    int tid = threadIdx.x;

    float x = v[tid];
    float ss = x * x;
    #pragma unroll
    for (int off = 16; off >= 1; off >>= 1) ss += __shfl_xor_sync(0xffffffff, ss, off);
    __shared__ float warp_ss[8];
    __shared__ float scale_sh;
    if ((tid & 31) == 0) warp_ss[tid >> 5] = ss;
    __syncthreads();
    if (tid == 0) {
        float tot = 0.f;
        #pragma unroll
        for (int w = 0; w < 8; w++) tot += warp_ss[w];
        scale_sh = g[l] * rsqrtf(tot);
    }
    __syncthreads();
    g_W[row * 256 + tid] = x * scale_sh;
    if (tid == 0) g_bias[row] = bb[l];

    int idx = blockIdx.x * 256 + tid;
    if (idx < B * LR) g_s[idx] = 0.f;
    if (idx < B * VD) g_vfinal[idx] = 0.f;
}

// ---------------------------------------------------------------------------
// Kernel C: fp16 tensor-core GEMM [65536x256] @ W^T[256x128] + fused epilogue.
// DOUBLE-BUFFERED dynamic smem: one __syncthreads per K-chunk (8 total).
// grid 512 (row tiles of 128), block 256 (8 warps: 4 m x 2 n).
__global__ void __launch_bounds__(256, 2) k_main(const float* __restrict__ Vmat)
{
    extern __shared__ char smem[];
    uint32_t (*As)[128][36] = (uint32_t(*)[128][36])(smem + SM_AS);
    uint32_t (*Bs)[128][36] = (uint32_t(*)[128][36])(smem + SM_BS);
    float* d_sh    = (float*)(smem + SM_D);
    float* s_sh    = (float*)(smem + SM_S);
    float* bias_sh = (float*)(smem + SM_BIAS);

    int tid = threadIdx.x;
    int lane = tid & 31, wid = tid >> 5;
    int warp_m = wid & 3, warp_n = wid >> 2;     // warp tile: 32 rows x 64 cols
    int qr = lane >> 2, qk = lane & 3;
    int tileRow0 = blockIdx.x * 128;
    int batch = blockIdx.x >> 4;                 // 16 tiles per batch

    if (tid < 128) { d_sh[tid] = 0.f; bias_sh[tid] = g_bias[tid]; }
    if (tid < 64) s_sh[tid] = 0.f;

    float acc[2][8][4];
    #pragma unroll
    for (int mt = 0; mt < 2; mt++)
        #pragma unroll
        for (int nt = 0; nt < 8; nt++)
            #pragma unroll
            for (int c = 0; c < 4; c++) acc[mt][nt][c] = 0.f;

    const float* Vbase = Vmat + (size_t)tileRow0 * VD;
    int lrow = tid >> 3;      // base row within the 32-row load slab
    int lkq  = tid & 7;       // float4 index within 32-k chunk

    // Per-lane ldmatrix base addresses within stage 0; stage offset added in loop.
    uint32_t sA = (uint32_t)__cvta_generic_to_shared(&As[0][0][0]);
    uint32_t sB = (uint32_t)__cvta_generic_to_shared(&Bs[0][0][0]);
    const uint32_t STAGE = 128u * 36u * 4u;      // 18432 bytes
    int l8 = lane & 7, lm = lane >> 3;           // lm = matrix index 0..3
    uint32_t a_base[2], b_base[4];
    #pragma unroll
    for (int mt = 0; mt < 2; mt++) {
        int row = warp_m * 32 + mt * 16 + (lm & 1) * 8 + l8;
        int kp  = (lm >> 1) * 4;
        a_base[mt] = sA + (uint32_t)(row * 36 + kp) * 4;
    }
    #pragma unroll
    for (int j = 0; j < 4; j++) {
        int c  = warp_n * 64 + (2 * j + (lm >> 1)) * 8 + l8;
        int kp = (lm & 1) * 4;
        b_base[j] = sB + (uint32_t)(c * 36 + kp) * 4;
    }

    float4 ra[4], rb[4];
    // prefetch chunk 0
    #pragma unroll
    for (int i = 0; i < 4; i++) {
        int r = i * 32 + lrow;
        ra[i] = *(const float4*)(Vbase + (size_t)r * VD + lkq * 4);
        rb[i] = *(const float4*)(g_W + r * 256 + lkq * 4);
    }

    for (int kc = 0; kc < 8; kc++) {
        int st = kc & 1;
        // STS into stage st (last read two chunks ago; ordered by barrier kc-1)
        #pragma unroll
        for (int i = 0; i < 4; i++) {
            int r = i * 32 + lrow;
            As[st][r][lkq * 2]     = pack_h2(ra[i].x, ra[i].y);
            As[st][r][lkq * 2 + 1] = pack_h2(ra[i].z, ra[i].w);
            Bs[st][r][lkq * 2]     = pack_h2(rb[i].x, rb[i].y);
            Bs[st][r][lkq * 2 + 1] = pack_h2(rb[i].z, rb[i].w);
        }
        if (kc < 7) {
            int k0 = (kc + 1) * 32;
            #pragma unroll
            for (int i = 0; i < 4; i++) {
                int r = i * 32 + lrow;
                ra[i] = *(const float4*)(Vbase + (size_t)r * VD + k0 + lkq * 4);
                rb[i] = *(const float4*)(g_W + r * 256 + k0 + lkq * 4);
            }
        }
        __syncthreads();
        uint32_t soff = st ? STAGE : 0u;
        // chunk = 32 k = 2 mma k16-steps
        #pragma unroll
        for (int ks = 0; ks < 2; ks++) {
            uint32_t koff = soff + ks * 32;
            uint32_t af[2][4];
            ldsm_x4(af[0], a_base[0] + koff);
            ldsm_x4(af[1], a_base[1] + koff);
            uint32_t bf[8][2];
            #pragma unroll
            for (int j = 0; j < 4; j++) {
                uint32_t t[4];
                ldsm_x4(t, b_base[j] + koff);
                bf[2 * j][0]     = t[0];
                bf[2 * j][1]     = t[1];
                bf[2 * j + 1][0] = t[2];
                bf[2 * j + 1][1] = t[3];
            }
            #pragma unroll
            for (int mt = 0; mt < 2; mt++)
                #pragma unroll
                for (int nt = 0; nt < 8; nt++)
                    mma_f16(acc[mt][nt], af[mt], bf[nt]);
        }
    }
    __syncthreads();

    // ---- epilogue: bias+relu, d per row, dr, store P=dr*right (fp16), s ----
    float be[8], bo[8];
    #pragma unroll
    for (int nt = 0; nt < 8; nt++) {
        int c0 = warp_n * 64 + nt * 8 + qk * 2;
        be[nt] = bias_sh[c0];
        bo[nt] = bias_sh[c0 + 1];
    }

    #pragma unroll
    for (int mt = 0; mt < 2; mt++) {
        #pragma unroll
        for (int h = 0; h < 2; h++) {
            float dpart = 0.f;
            #pragma unroll
            for (int nt = 0; nt < 8; nt++) {
                float rv = fmaxf(acc[mt][nt][h * 2]     + be[nt], 0.f);
                float lv = fmaxf(acc[mt][nt][h * 2 + 1] + bo[nt], 0.f);
                acc[mt][nt][h * 2] = rv;
                acc[mt][nt][h * 2 + 1] = lv;
                dpart = fmaf(rv, lv, dpart);
            }
            dpart += __shfl_xor_sync(0xffffffff, dpart, 1);
            dpart += __shfl_xor_sync(0xffffffff, dpart, 2);
            if (qk == 0) {
                int rl = warp_m * 32 + mt * 16 + h * 8 + qr;
                atomicAdd(&d_sh[rl], dpart);
            }
        }
    }
    __syncthreads();

    float s_t[8];
    #pragma unroll
    for (int nt = 0; nt < 8; nt++) s_t[nt] = 0.f;

    #pragma unroll
    for (int mt = 0; mt < 2; mt++) {
        #pragma unroll
        for (int h = 0; h < 2; h++) {
            int rl = warp_m * 32 + mt * 16 + h * 8 + qr;
            float dr = rsqrtf(d_sh[rl] + EPS_DIAG);
            int row = tileRow0 + rl;
            __half* pp = g_P + (size_t)row * LR + warp_n * 32;
            #pragma unroll
            for (int nt = 0; nt < 8; nt++) {
                pp[nt * 4 + qk] = __float2half(dr * acc[mt][nt][h * 2]);
                s_t[nt] = fmaf(dr, acc[mt][nt][h * 2 + 1], s_t[nt]);
            }
        }
    }
    #pragma unroll
    for (int off = 4; off <= 16; off <<= 1)
        #pragma unroll
        for (int nt = 0; nt < 8; nt++)
            s_t[nt] += __shfl_xor_sync(0xffffffff, s_t[nt], off);
    if (qr == 0) {
        #pragma unroll
        for (int nt = 0; nt < 8; nt++)
            atomicAdd(&s_sh[warp_n * 32 + nt * 4 + qk], s_t[nt]);
    }
    __syncthreads();
    if (tid < 64) atomicAdd(&g_s[batch * LR + tid], s_sh[tid]);
}

// ---------------------------------------------------------------------------
// Kernel D: c[m] = N+1 - s.P[m]; v_final += (1/N)*c[m]*Vmat[m,:]
// grid (4, 32), block 256. (61.7us-measured version)
__global__ void __launch_bounds__(256) k_final(const float* __restrict__ Vmat)
{
    __shared__ float s_sh[64];
    __shared__ float c_sh[512];
    __shared__ float red[4][256];
    int tid = threadIdx.x;
    int b = blockIdx.y;
    int m0 = blockIdx.x * 512;

    if (tid < 64) s_sh[tid] = g_s[b * LR + tid];
    __syncthreads();

    #pragma unroll
    for (int i = 0; i < 2; i++) {
        int row = b * N + m0 + tid + i * 256;
        const uint4* pp = (const uint4*)(g_P + (size_t)row * LR);
        float dot = 0.f;
        #pragma unroll
        for (int q = 0; q < 8; q++) {
            uint4 u = pp[q];
            float2 f0 = __half22float2(*(__half2*)&u.x);
            float2 f1 = __half22float2(*(__half2*)&u.y);
            float2 f2 = __half22float2(*(__half2*)&u.z);
            float2 f3 = __half22float2(*(__half2*)&u.w);
            const float* sv = &s_sh[q * 8];
            dot = fmaf(f0.x, sv[0], dot); dot = fmaf(f0.y, sv[1], dot);
            dot = fmaf(f1.x, sv[2], dot); dot = fmaf(f1.y, sv[3], dot);
            dot = fmaf(f2.x, sv[4], dot); dot = fmaf(f2.y, sv[5], dot);
            dot = fmaf(f3.x, sv[6], dot); dot = fmaf(f3.y, sv[7], dot);
        }
        c_sh[tid + i * 256] = (float)(N + 1) - dot;
    }
    __syncthreads();

    int g = tid >> 6;
    int c4 = (tid & 63) * 4;
    const float* Vp = Vmat + ((size_t)(b * N + m0 + g * 128)) * VD + c4;
    const float* cp = &c_sh[g * 128];
    float4 vac = make_float4(0.f, 0.f, 0.f, 0.f);
    #pragma unroll 8
    for (int j = 0; j < 128; j++) {
        float4 v = *(const float4*)(Vp + (size_t)j * VD);
        float cc = cp[j];
        vac.x = fmaf(cc, v.x, vac.x);
        vac.y = fmaf(cc, v.y, vac.y);
        vac.z = fmaf(cc, v.z, vac.z);
        vac.w = fmaf(cc, v.w, vac.w);
    }
    *(float4*)&red[g][c4] = vac;
    __syncthreads();

    float sum = red[0][tid] + red[1][tid] + red[2][tid] + red[3][tid];
    atomicAdd(&g_vfinal[b * VD + tid], sum * (1.0f / (float)N));
}

// ---------------------------------------------------------------------------
// Kernel E: feat = v_final @ W_lin^T + b_lin; BatchNorm over B (biased var).
// grid 256, block 128. (61.7us-measured version)
__global__ void __launch_bounds__(128) k_bn(const float* __restrict__ W_lin,
                                            const float* __restrict__ b_lin,
                                            const float* __restrict__ gamma,
                                            const float* __restrict__ beta,
                                            float* __restrict__ out)
{
    int e = blockIdx.x;
    int tid = threadIdx.x;
    __shared__ float4 w_sh[64];
    __shared__ float feats[32];

    if (tid < 64) w_sh[tid] = ((const float4*)(W_lin + e * VD))[tid];
    __syncthreads();

    int bat = tid >> 2;
    int q0  = tid & 3;
    const float4* vr = (const float4*)(g_vfinal + bat * VD);
    float dot = 0.f;
    #pragma unroll
    for (int q = 0; q < 16; q++) {
        float4 v = vr[q * 4 + q0];
        float4 w = w_sh[q * 4 + q0];
        dot = fmaf(v.x, w.x, dot);
        dot = fmaf(v.y, w.y, dot);
        dot = fmaf(v.z, w.z, dot);
        dot = fmaf(v.w, w.w, dot);
    }
    dot += __shfl_xor_sync(0xffffffff, dot, 1);
    dot += __shfl_xor_sync(0xffffffff, dot, 2);
    if (q0 == 0) feats[bat] = dot + b_lin[e];
    __syncthreads();

    if (tid < 32) {
        float f = feats[tid];
        float mu = f;
        #pragma unroll
        for (int off = 16; off >= 1; off >>= 1) mu += __shfl_xor_sync(0xffffffff, mu, off);
        mu *= (1.0f / 32.0f);
        float df = f - mu;
        float vv = df * df;
        #pragma unroll
        for (int off = 16; off >= 1; off >>= 1) vv += __shfl_xor_sync(0xffffffff, vv, off);
        vv *= (1.0f / 32.0f);
        out[tid * EMB + e] = df * rsqrtf(vv + EPS_BN) * gamma[e] + beta[e];
    }
}

// ---------------------------------------------------------------------------
extern "C" void kernel_launch(void* const* d_in, const int* in_sizes, int n_in,
                              void* d_out, int out_size)
{
    const float* Vmat  = (const float*)d_in[0];
    const float* U1_v  = (const float*)d_in[1];
    const float* U1_g  = (const float*)d_in[2];
    const float* U1_b  = (const float*)d_in[3];
    const float* U2_v  = (const float*)d_in[4];
    const float* U2_g  = (const float*)d_in[5];
    const float* U2_b  = (const float*)d_in[6];
    const float* W_lin = (const float*)d_in[7];
    const float* b_lin = (const float*)d_in[8];
    const float* gamma = (const float*)d_in[9];
    const float* beta  = (const float*)d_in[10];
    float* out = (float*)d_out;

    static int smem_set = 0;
    if (!smem_set) {
        cudaFuncSetAttribute(k_main, cudaFuncAttributeMaxDynamicSharedMemorySize, SMEM_MAIN);
        smem_set = 1;
    }

    k_weightnorm<<<128, 256>>>(U1_v, U1_g, U1_b, U2_v, U2_g, U2_b);
    k_main<<<ROWS / 128, 256, SMEM_MAIN>>>(Vmat);
    k_final<<<dim3(4, B), 256>>>(Vmat);
    k_bn<<<EMB, 128>>>(W_lin, b_lin, gamma, beta, out);
}